// round 9
// baseline (speedup 1.0000x reference)
#include <cuda_runtime.h>
#include <cuda_bf16.h>
#include <cstdint>

#define U_N 4096
#define I_N 8192
#define ROWS_T 12288

// ---------------- static device scratch (no runtime allocation) ----------------
__device__ __align__(256) uint32_t g_bitsUI[(size_t)U_N * 256]; // [u][i/32]
__device__ __align__(256) uint32_t g_bitsIU[(size_t)I_N * 128]; // [i][u/32]
__device__ float g_ru[U_N];
__device__ float g_ri[I_N];
// GEMM B operands, layout [n][k]: n<64 = hi of dim n, n>=64 = lo of dim n-64
__device__ __align__(256) __nv_bfloat16 g_B1[(size_t)128 * U_N]; // k = user
__device__ __align__(256) __nv_bfloat16 g_B2[(size_t)128 * I_N]; // k = item
__device__ __align__(256) float g_raw1[(size_t)I_N * 128];
__device__ __align__(256) float g_raw2[(size_t)2 * U_N * 128];   // 2 K-splits
__device__ __align__(256) float g_x[(size_t)ROWS_T * 64];
__device__ __align__(256) float g_acc[(size_t)ROWS_T * 64];

// ---------------- P1: pack adjacency bits (both orientations) ----------------
__global__ __launch_bounds__(256) void pack_kernel(const int* __restrict__ edge) {
    int gw   = (blockIdx.x * 256 + threadIdx.x) >> 5;  // 32768 warps: 128 u-tiles x 256 i-tiles
    int lane = threadIdx.x & 31;
    int tu = gw >> 8;
    int ti = gw & 255;
    const int* base = edge + (size_t)tu * 32 * 8192 + ti * 32 + lane;
    uint32_t my = 0, uiw = 0;
    #pragma unroll 4
    for (int r = 0; r < 32; r++) {
        int val = base[(size_t)r * 8192];
        unsigned m = __ballot_sync(0xffffffffu, val != 0);
        my |= (uint32_t)(val != 0) << r;
        if (lane == r) uiw = m;
    }
    g_bitsUI[(size_t)(tu * 32 + lane) * 256 + ti] = uiw;
    g_bitsIU[(size_t)(ti * 32 + lane) * 128 + tu] = my;
}

// ---------------- P2: degrees -> rsqrt scales ----------------
__global__ __launch_bounds__(256) void scales_kernel() {
    int gw   = (blockIdx.x * 256 + threadIdx.x) >> 5;  // 12288 warps
    int lane = threadIdx.x & 31;
    int s = 0;
    if (gw < U_N) {
        const uint32_t* w = g_bitsUI + (size_t)gw * 256;
        for (int j = lane; j < 256; j += 32) s += __popc(w[j]);
        for (int o = 16; o; o >>= 1) s += __shfl_down_sync(0xffffffffu, s, o);
        if (!lane) g_ru[gw] = s ? rsqrtf((float)s) : 0.f;
    } else {
        int i = gw - U_N;
        const uint32_t* w = g_bitsIU + (size_t)i * 128;
        for (int j = lane; j < 128; j += 32) s += __popc(w[j]);
        for (int o = 16; o; o >>= 1) s += __shfl_down_sync(0xffffffffu, s, o);
        if (!lane) g_ri[i] = s ? rsqrtf((float)s) : 0.f;
    }
}

// ---------------- P3: per-layer operand prep (scale + hi/lo bf16 split, transpose) --
__global__ __launch_bounds__(256) void prep_kernel(const float* __restrict__ xin, int layer) {
    __shared__ float xs[64][65];
    int b = blockIdx.x, tid = threadIdx.x;
    const float* src = (layer == 0) ? xin : g_x;
    int k0, srow, K;
    const float* sc;
    __nv_bfloat16* dst;
    if (b < 64) { k0 = b * 64;        srow = k0;         sc = g_ru; dst = g_B1; K = U_N; }
    else        { k0 = (b - 64) * 64; srow = U_N + k0;   sc = g_ri; dst = g_B2; K = I_N; }
    for (int i = tid; i < 4096; i += 256)
        xs[i >> 6][i & 63] = src[(size_t)(srow + (i >> 6)) * 64 + (i & 63)];
    __syncthreads();
    int ul = tid & 63, db = tid >> 6;
    float s = sc[k0 + ul];
    #pragma unroll
    for (int j = 0; j < 16; j++) {
        int d = db + j * 4;
        float v = s * xs[ul][d];
        __nv_bfloat16 hi = __float2bfloat16(v);
        __nv_bfloat16 lo = __float2bfloat16(v - __bfloat162float(hi));
        dst[(size_t)d * K + k0 + ul] = hi;
        dst[(size_t)(d + 64) * K + k0 + ul] = lo;
    }
}

// ---------------- GEMM: bit-matrix x bf16, fp32 accum via mma.sync ----------------
__device__ __forceinline__ uint32_t pack2(uint32_t w) {
    return ((w & 1u) ? 0x3F80u : 0u) | ((w & 2u) ? 0x3F800000u : 0u);
}
__device__ __forceinline__ void mma16816(float* c, uint32_t a0, uint32_t a1, uint32_t a2,
                                         uint32_t a3, uint32_t b0, uint32_t b1) {
    asm volatile(
        "mma.sync.aligned.m16n8k16.row.col.f32.bf16.bf16.f32 "
        "{%0,%1,%2,%3}, {%4,%5,%6,%7}, {%8,%9}, {%0,%1,%2,%3};"
        : "+f"(c[0]), "+f"(c[1]), "+f"(c[2]), "+f"(c[3])
        : "r"(a0), "r"(a1), "r"(a2), "r"(a3), "r"(b0), "r"(b1));
}
__device__ __forceinline__ void cp16(void* dst_smem, const void* src) {
    uint32_t d = (uint32_t)__cvta_generic_to_shared(dst_smem);
    asm volatile("cp.async.cg.shared.global [%0], [%1], 16;" :: "r"(d), "l"(src));
}

__global__ __launch_bounds__(512) void gemm_kernel() {
    __shared__ __align__(128) __nv_bfloat16 Bs[2][128][72];  // dbl buf, pad 72: no conflicts
    int b = blockIdx.x, tid = threadIdx.x;
    const uint32_t* bits;
    const __nv_bfloat16* Bg;
    float* raw;
    int m0, wpr, K, kbeg;
    if (b < 64) {            // dir1: top = A^T side, M=8192, K=4096
        bits = g_bitsIU; Bg = g_B1; raw = g_raw1;
        m0 = b * 128; wpr = 128; K = U_N; kbeg = 0;
    } else {                 // dir2: bot = A side, M=4096, K=8192, split-K=2
        int bb = b - 64, split = bb >> 5, mb = bb & 31;
        bits = g_bitsUI; Bg = g_B2; raw = g_raw2 + (size_t)split * U_N * 128;
        m0 = mb * 128; wpr = 256; K = I_N; kbeg = split * 4096;
    }
    int warp = tid >> 5, lane = tid & 31, g = lane >> 2, tig = lane & 3;
    int wm = warp >> 2, wn = warp & 3;      // 4x4 warp grid, each 32(M) x 32(N)
    int mw = m0 + wm * 32;
    int nw = wn * 32;
    float c[2][4][4];
    #pragma unroll
    for (int mt = 0; mt < 2; mt++)
        #pragma unroll
        for (int tn = 0; tn < 4; tn++)
            #pragma unroll
            for (int q = 0; q < 4; q++) c[mt][tn][q] = 0.f;

    // staging geometry: chunk = [128 n][64 k] bf16 = 1024 x 16B; 512 threads x 2
    int sn0 = tid >> 3, sk0 = (tid & 7) * 8;          // iter 0: n 0..63
    const __nv_bfloat16* sp0 = Bg + (size_t)sn0 * K + sk0;
    const __nv_bfloat16* sp1 = sp0 + (size_t)64 * K;  // iter 1: n 64..127

    // prologue: stage chunk 0, prefetch bits 0
    {
        int kg = kbeg;
        cp16(&Bs[0][sn0][sk0], sp0 + kg);
        cp16(&Bs[0][sn0 + 64][sk0], sp1 + kg);
        asm volatile("cp.async.commit_group;" ::: "memory");
    }
    uint32_t wv[4][2], wvn[4][2];
    #pragma unroll
    for (int rid = 0; rid < 4; rid++) {
        uint2 t2 = *(const uint2*)(bits + (size_t)(mw + g + rid * 8) * wpr + (kbeg >> 5));
        wv[rid][0] = t2.x; wv[rid][1] = t2.y;
    }

    for (int ch = 0; ch < 64; ch++) {
        int cur = ch & 1;
        if (ch < 63) {
            int kg = kbeg + (ch + 1) * 64;
            cp16(&Bs[cur ^ 1][sn0][sk0], sp0 + kg);
            cp16(&Bs[cur ^ 1][sn0 + 64][sk0], sp1 + kg);
            asm volatile("cp.async.commit_group;" ::: "memory");
            #pragma unroll
            for (int rid = 0; rid < 4; rid++) {
                uint2 t2 = *(const uint2*)(bits + (size_t)(mw + g + rid * 8) * wpr + (kg >> 5));
                wvn[rid][0] = t2.x; wvn[rid][1] = t2.y;
            }
            asm volatile("cp.async.wait_group 1;" ::: "memory");
        } else {
            asm volatile("cp.async.wait_group 0;" ::: "memory");
        }
        __syncthreads();
        #pragma unroll
        for (int s = 0; s < 4; s++) {      // 4 x K16 steps
            uint32_t bb_[4][2];
            #pragma unroll
            for (int tn = 0; tn < 4; tn++) {
                int n = nw + tn * 8 + g;
                bb_[tn][0] = *(const uint32_t*)(&Bs[cur][n][s * 16 + 2 * tig]);
                bb_[tn][1] = *(const uint32_t*)(&Bs[cur][n][s * 16 + 2 * tig + 8]);
            }
            int sh = (s & 1) * 16 + 2 * tig;
            #pragma unroll
            for (int mt = 0; mt < 2; mt++) {
                uint32_t wr  = wv[2 * mt][s >> 1] >> sh;
                uint32_t wr8 = wv[2 * mt + 1][s >> 1] >> sh;
                uint32_t a0 = pack2(wr), a1 = pack2(wr8);
                uint32_t a2 = pack2(wr >> 8), a3 = pack2(wr8 >> 8);
                #pragma unroll
                for (int tn = 0; tn < 4; tn++)
                    mma16816(c[mt][tn], a0, a1, a2, a3, bb_[tn][0], bb_[tn][1]);
            }
        }
        __syncthreads();                   // protect buf cur before ch+2 staging
        #pragma unroll
        for (int rid = 0; rid < 4; rid++) {
            wv[rid][0] = wvn[rid][0]; wv[rid][1] = wvn[rid][1];
        }
    }
    #pragma unroll
    for (int mt = 0; mt < 2; mt++)
        #pragma unroll
        for (int tn = 0; tn < 4; tn++) {
            int row = mw + mt * 16 + g;
            int col = nw + tn * 8 + 2 * tig;
            float* p = raw + (size_t)row * 128 + col;
            p[0] = c[mt][tn][0]; p[1] = c[mt][tn][1];
            p += 8 * 128;
            p[0] = c[mt][tn][2]; p[1] = c[mt][tn][3];
        }
}

// ---------------- combine: hi+lo, split-K sum, degree scale, concat, accumulate ----
__global__ __launch_bounds__(256) void combine_kernel(float* out, int layer) {
    int idx = blockIdx.x * 256 + threadIdx.x;  // 786432 elems
    int row = idx >> 6, d = idx & 63;
    float v;
    if (row < I_N) {
        const float* p = g_raw1 + (size_t)row * 128 + d;
        v = g_ri[row] * (p[0] + p[64]);
    } else {
        int u = row - I_N;
        const float* p = g_raw2 + (size_t)u * 128 + d;
        const float* q = p + (size_t)U_N * 128;
        v = g_ru[u] * (p[0] + p[64] + q[0] + q[64]);
    }
    g_x[idx] = v;
    float a = (layer == 0) ? v : (g_acc[idx] + v);
    g_acc[idx] = a;
    if (out) out[idx] = a * 0.25f;
}

// ---------------- launch ----------------
extern "C" void kernel_launch(void* const* d_in, const int* in_sizes, int n_in,
                              void* d_out, int out_size) {
    const float* x    = (const float*)d_in[0];
    const int*   edge = (const int*)d_in[1];
    float*       out  = (float*)d_out;
    pack_kernel<<<4096, 256>>>(edge);
    scales_kernel<<<1536, 256>>>();
    for (int l = 0; l < 3; l++) {
        prep_kernel<<<192, 256>>>(x, l);
        gemm_kernel<<<128, 512>>>();
        combine_kernel<<<3072, 256>>>(l == 2 ? out : nullptr, l);
    }
}

// round 11
// speedup vs baseline: 1.1779x; 1.1779x over previous
#include <cuda_runtime.h>
#include <cuda_bf16.h>
#include <cstdint>

#define U_N 4096
#define I_N 8192
#define ROWS_T 12288
#define PITCH 72                       // bf16 elems per SMEM row (pad for banks)
#define TILEB (128 * PITCH * 2)        // 18432 bytes per tile
#define GSMEM_TOTAL (4 * TILEB)        // A0 A1 B0 B1 = 73728 bytes

// ---------------- static device scratch (no runtime allocation) ----------------
__device__ __align__(256) uint32_t g_bitsUI[(size_t)U_N * 256]; // [u][i/32]
__device__ __align__(256) uint32_t g_bitsIU[(size_t)I_N * 128]; // [i][u/32]
__device__ float g_ru[U_N];
__device__ float g_ri[I_N];
// GEMM B operands, layout [n][k]: n<64 = hi of dim n, n>=64 = lo of dim n-64
__device__ __align__(256) __nv_bfloat16 g_B1[(size_t)128 * U_N]; // k = user
__device__ __align__(256) __nv_bfloat16 g_B2[(size_t)128 * I_N]; // k = item
__device__ __align__(256) float g_raw1[(size_t)I_N * 128];
__device__ __align__(256) float g_raw2[(size_t)2 * U_N * 128];   // 2 K-splits
__device__ __align__(256) float g_x[(size_t)ROWS_T * 64];
__device__ __align__(256) float g_acc[(size_t)ROWS_T * 64];

// ---------------- P1: pack adjacency bits (both orientations) ----------------
__global__ __launch_bounds__(256) void pack_kernel(const int* __restrict__ edge) {
    int gw   = (blockIdx.x * 256 + threadIdx.x) >> 5;
    int lane = threadIdx.x & 31;
    int tu = gw >> 8;
    int ti = gw & 255;
    const int* base = edge + (size_t)tu * 32 * 8192 + ti * 32 + lane;
    uint32_t my = 0, uiw = 0;
    #pragma unroll 4
    for (int r = 0; r < 32; r++) {
        int val = base[(size_t)r * 8192];
        unsigned m = __ballot_sync(0xffffffffu, val != 0);
        my |= (uint32_t)(val != 0) << r;
        if (lane == r) uiw = m;
    }
    g_bitsUI[(size_t)(tu * 32 + lane) * 256 + ti] = uiw;
    g_bitsIU[(size_t)(ti * 32 + lane) * 128 + tu] = my;
}

// ---------------- P2: degrees -> rsqrt scales ----------------
__global__ __launch_bounds__(256) void scales_kernel() {
    int gw   = (blockIdx.x * 256 + threadIdx.x) >> 5;
    int lane = threadIdx.x & 31;
    int s = 0;
    if (gw < U_N) {
        const uint32_t* w = g_bitsUI + (size_t)gw * 256;
        for (int j = lane; j < 256; j += 32) s += __popc(w[j]);
        for (int o = 16; o; o >>= 1) s += __shfl_down_sync(0xffffffffu, s, o);
        if (!lane) g_ru[gw] = s ? rsqrtf((float)s) : 0.f;
    } else {
        int i = gw - U_N;
        const uint32_t* w = g_bitsIU + (size_t)i * 128;
        for (int j = lane; j < 128; j += 32) s += __popc(w[j]);
        for (int o = 16; o; o >>= 1) s += __shfl_down_sync(0xffffffffu, s, o);
        if (!lane) g_ri[i] = s ? rsqrtf((float)s) : 0.f;
    }
}

// ---------------- P3: per-layer operand prep (scale + hi/lo bf16 split) ----------
__global__ __launch_bounds__(256) void prep_kernel(const float* __restrict__ xin, int layer) {
    __shared__ float xs[64][65];
    int b = blockIdx.x, tid = threadIdx.x;
    const float* src = (layer == 0) ? xin : g_x;
    int k0, srow, K;
    const float* sc;
    __nv_bfloat16* dst;
    if (b < 64) { k0 = b * 64;        srow = k0;         sc = g_ru; dst = g_B1; K = U_N; }
    else        { k0 = (b - 64) * 64; srow = U_N + k0;   sc = g_ri; dst = g_B2; K = I_N; }
    for (int i = tid; i < 4096; i += 256)
        xs[i >> 6][i & 63] = src[(size_t)(srow + (i >> 6)) * 64 + (i & 63)];
    __syncthreads();
    int ul = tid & 63, db = tid >> 6;
    float s = sc[k0 + ul];
    #pragma unroll
    for (int j = 0; j < 16; j++) {
        int d = db + j * 4;
        float v = s * xs[ul][d];
        __nv_bfloat16 hi = __float2bfloat16(v);
        __nv_bfloat16 lo = __float2bfloat16(v - __bfloat162float(hi));
        dst[(size_t)d * K + k0 + ul] = hi;
        dst[(size_t)(d + 64) * K + k0 + ul] = lo;
    }
}

// ---------------- GEMM helpers ----------------
__device__ __forceinline__ void mma16816(float* c, uint32_t a0, uint32_t a1, uint32_t a2,
                                         uint32_t a3, uint32_t b0, uint32_t b1) {
    asm volatile(
        "mma.sync.aligned.m16n8k16.row.col.f32.bf16.bf16.f32 "
        "{%0,%1,%2,%3}, {%4,%5,%6,%7}, {%8,%9}, {%0,%1,%2,%3};"
        : "+f"(c[0]), "+f"(c[1]), "+f"(c[2]), "+f"(c[3])
        : "r"(a0), "r"(a1), "r"(a2), "r"(a3), "r"(b0), "r"(b1));
}
__device__ __forceinline__ void ldsm4(uint32_t* r, uint32_t addr) {
    asm volatile("ldmatrix.sync.aligned.m8n8.x4.shared.b16 {%0,%1,%2,%3}, [%4];"
                 : "=r"(r[0]), "=r"(r[1]), "=r"(r[2]), "=r"(r[3]) : "r"(addr));
}
__device__ __forceinline__ void cp16(uint32_t dst_smem, const void* src) {
    asm volatile("cp.async.cg.shared.global [%0], [%1], 16;" :: "r"(dst_smem), "l"(src));
}
__device__ __forceinline__ uint32_t smem_u32(const void* p) {
    uint32_t a;
    asm("{ .reg .u64 t; cvta.to.shared.u64 t, %1; cvt.u32.u64 %0, t; }" : "=r"(a) : "l"(p));
    return a;
}
// expand 16 adjacency bits -> 16 bf16 {0,1} (32 bytes) at dst
__device__ __forceinline__ void expand16(char* dst, uint32_t bits16) {
    uint32_t pv[8];
    #pragma unroll
    for (int p = 0; p < 8; p++) {
        uint32_t t2 = (bits16 >> (2 * p)) & 3u;
        pv[p] = ((t2 & 1u) | ((t2 & 2u) << 15)) * 0x3F80u;
    }
    *(uint4*)dst        = make_uint4(pv[0], pv[1], pv[2], pv[3]);
    *(uint4*)(dst + 16) = make_uint4(pv[4], pv[5], pv[6], pv[7]);
}

// ---------------- GEMM: bits -> SMEM A-tile, ldmatrix + mma.sync ----------------
__global__ __launch_bounds__(512) void gemm_kernel() {
    extern __shared__ __align__(128) char dyn[];
    char* Atile[2] = {dyn, dyn + TILEB};
    char* Btile[2] = {dyn + 2 * TILEB, dyn + 3 * TILEB};
    uint32_t sb = smem_u32(dyn);

    int b = blockIdx.x, tid = threadIdx.x;
    const uint32_t* bits;
    const __nv_bfloat16* Bg;
    float* raw;
    int m0, wpr, K, kbeg;
    if (b < 64) {            // dir1: top = A^T side, M=8192, K=4096
        bits = g_bitsIU; Bg = g_B1; raw = g_raw1;
        m0 = b * 128; wpr = 128; K = U_N; kbeg = 0;
    } else {                 // dir2: bot = A side, M=4096, K=8192, split-K=2
        int bb = b - 64, split = bb >> 5, mb = bb & 31;
        bits = g_bitsUI; Bg = g_B2; raw = g_raw2 + (size_t)split * U_N * 128;
        m0 = mb * 128; wpr = 256; K = I_N; kbeg = split * 4096;
    }

    int warp = tid >> 5, lane = tid & 31, g = lane >> 2, tig = lane & 3;
    int wm = warp >> 2, wn = warp & 3;           // 4x4 warp grid, 32(M) x 32(N) each

    // --- expansion geometry: thread -> (row, quarter) of the 128x64 A chunk
    int er = tid >> 2, eq = tid & 3;             // row 0..127, 16-bit quarter 0..3
    int esh = (eq & 1) * 16;
    const uint32_t* bitq = bits + (size_t)(m0 + er) * wpr + (kbeg >> 5) + (eq >> 1);
    int eoff = er * (PITCH * 2) + eq * 32;       // byte offset in A tile

    // --- B staging geometry: chunk = [128 n][64 k] bf16; thread covers 2 rows x 16B
    int sn0 = tid >> 3, sk0 = (tid & 7) * 8;
    const __nv_bfloat16* sp0 = Bg + (size_t)sn0 * K + kbeg + sk0;
    const __nv_bfloat16* sp1 = sp0 + (size_t)64 * K;
    int bo0 = sn0 * (PITCH * 2) + sk0 * 2;
    int bo1 = (sn0 + 64) * (PITCH * 2) + sk0 * 2;

    // --- ldmatrix address bases (per buffer)
    // A: row = wm*32 + (lane&15) [+16 for mt=1], col = s*16 + (lane>>4)*8
    uint32_t aAddr[2], bAddr[2];
    {
        int arow = wm * 32 + (lane & 15);
        int acol = (lane >> 4) * 8;
        int brow = wn * 32 + (lane & 7) + ((lane >> 4) & 1) * 8;
        int bcol = ((lane >> 3) & 1) * 8;
        for (int s2 = 0; s2 < 2; s2++) {
            aAddr[s2] = sb + (uint32_t)(s2 * TILEB) + arow * (PITCH * 2) + acol * 2;
            bAddr[s2] = sb + (uint32_t)(2 * TILEB + s2 * TILEB) + brow * (PITCH * 2) + bcol * 2;
        }
    }

    float c[2][4][4];
    #pragma unroll
    for (int mt = 0; mt < 2; mt++)
        #pragma unroll
        for (int tn = 0; tn < 4; tn++)
            #pragma unroll
            for (int q = 0; q < 4; q++) c[mt][tn][q] = 0.f;

    // prologue: expand A(0), stage B(0), prefetch bits(1)
    expand16(Atile[0] + eoff, bitq[0] >> esh);
    cp16(sb + 2 * TILEB + bo0, sp0);
    cp16(sb + 2 * TILEB + bo1, sp1);
    asm volatile("cp.async.commit_group;" ::: "memory");
    uint32_t wext = bitq[2];

    for (int ch = 0; ch < 64; ch++) {
        int cur = ch & 1, nx = cur ^ 1;
        if (ch < 63) {
            cp16(sb + 2 * TILEB + nx * TILEB + bo0, sp0 + (size_t)(ch + 1) * 64);
            cp16(sb + 2 * TILEB + nx * TILEB + bo1, sp1 + (size_t)(ch + 1) * 64);
            asm volatile("cp.async.commit_group;" ::: "memory");
            expand16(Atile[nx] + eoff, wext >> esh);
            wext = bitq[(ch + 2 < 64) ? (ch + 2) * 2 : 0];
            asm volatile("cp.async.wait_group 1;" ::: "memory");
        } else {
            asm volatile("cp.async.wait_group 0;" ::: "memory");
        }
        __syncthreads();
        #pragma unroll
        for (int s = 0; s < 4; s++) {
            uint32_t aF[2][4], bF[2][4];
            ldsm4(aF[0], aAddr[cur] + s * 32);
            ldsm4(aF[1], aAddr[cur] + s * 32 + 16 * (PITCH * 2));
            ldsm4(bF[0], bAddr[cur] + s * 32);
            ldsm4(bF[1], bAddr[cur] + s * 32 + 16 * (PITCH * 2));
            #pragma unroll
            for (int mt = 0; mt < 2; mt++)
                #pragma unroll
                for (int tp = 0; tp < 2; tp++) {
                    mma16816(c[mt][2 * tp],     aF[mt][0], aF[mt][1], aF[mt][2], aF[mt][3],
                             bF[tp][0], bF[tp][1]);
                    mma16816(c[mt][2 * tp + 1], aF[mt][0], aF[mt][1], aF[mt][2], aF[mt][3],
                             bF[tp][2], bF[tp][3]);
                }
        }
        __syncthreads();
    }
    // store: c[mt][2*tp+hf] -> rows (wm*32+mt*16+g, +8), cols wn*32+tp*16+hf*8+2*tig
    #pragma unroll
    for (int mt = 0; mt < 2; mt++)
        #pragma unroll
        for (int tn = 0; tn < 4; tn++) {
            int row = m0 + wm * 32 + mt * 16 + g;
            int col = wn * 32 + (tn >> 1) * 16 + (tn & 1) * 8 + 2 * tig;
            float* p = raw + (size_t)row * 128 + col;
            p[0] = c[mt][tn][0]; p[1] = c[mt][tn][1];
            p += 8 * 128;
            p[0] = c[mt][tn][2]; p[1] = c[mt][tn][3];
        }
}

// ---------------- combine: hi+lo, split-K sum, degree scale, concat, accumulate ----
__global__ __launch_bounds__(256) void combine_kernel(float* out, int layer) {
    int idx = blockIdx.x * 256 + threadIdx.x;  // 786432 elems
    int row = idx >> 6, d = idx & 63;
    float v;
    if (row < I_N) {
        const float* p = g_raw1 + (size_t)row * 128 + d;
        v = g_ri[row] * (p[0] + p[64]);
    } else {
        int u = row - I_N;
        const float* p = g_raw2 + (size_t)u * 128 + d;
        const float* q = p + (size_t)U_N * 128;
        v = g_ru[u] * (p[0] + p[64] + q[0] + q[64]);
    }
    g_x[idx] = v;
    float a = (layer == 0) ? v : (g_acc[idx] + v);
    g_acc[idx] = a;
    if (out) out[idx] = a * 0.25f;
}

// ---------------- launch ----------------
extern "C" void kernel_launch(void* const* d_in, const int* in_sizes, int n_in,
                              void* d_out, int out_size) {
    const float* x    = (const float*)d_in[0];
    const int*   edge = (const int*)d_in[1];
    float*       out  = (float*)d_out;
    cudaFuncSetAttribute(gemm_kernel, cudaFuncAttributeMaxDynamicSharedMemorySize, GSMEM_TOTAL);
    pack_kernel<<<4096, 256>>>(edge);
    scales_kernel<<<1536, 256>>>();
    for (int l = 0; l < 3; l++) {
        prep_kernel<<<192, 256>>>(x, l);
        gemm_kernel<<<128, 512, GSMEM_TOTAL>>>();
        combine_kernel<<<3072, 256>>>(l == 2 ? out : nullptr, l);
    }
}